// round 1
// baseline (speedup 1.0000x reference)
#include <cuda_runtime.h>
#include <cstdint>

// ---------------------------------------------------------------------------
// TopKRouter: logits = x @ gate_w^T ; softmax ; top-2 (+renorm) ; aux loss.
// x: [T=16384, D=2048] fp32, gate_w: [E=64, D=2048] fp32.
// d_out (float32, 4T+1):
//   [0,   2T) : top_indices (as float), token-major, K=2
//   [2T,  4T) : top_weights (renormalized), token-major, K=2
//   [4T]      : aux_loss
// ---------------------------------------------------------------------------

#define DIM      2048
#define NEXP     64
#define TPC      64        // tokens per CTA
#define KC       64        // K chunk
#define NCHUNK   (DIM / KC)
#define THREADS  128
#define XPAD     66        // xs row stride (floats) -> conflict-free token reads
#define EPAD     66        // ws row stride (floats)
#define MAXCTA   1024

// Per-CTA partial-reduction scratch (written fresh every launch -> no zeroing,
// fixed summation order in finalize -> deterministic across graph replays).
__device__ float g_P[MAXCTA * NEXP];
__device__ int   g_cnt[MAXCTA * NEXP];
__device__ float g_lse2[MAXCTA];

__device__ __forceinline__ unsigned long long pack2(float a, float b) {
    unsigned long long r;
    asm("mov.b64 %0, {%1, %2};" : "=l"(r) : "f"(a), "f"(b));
    return r;
}
__device__ __forceinline__ float2 unpack2(unsigned long long v) {
    float2 r;
    asm("mov.b64 {%0, %1}, %2;" : "=f"(r.x), "=f"(r.y) : "l"(v));
    return r;
}
// Packed fp32 FMA: d = a*b + d (elementwise on 2 lanes). 2 FMA / instruction.
__device__ __forceinline__ void fma2(unsigned long long& d,
                                     unsigned long long a,
                                     unsigned long long b) {
    asm("fma.rn.f32x2 %0, %1, %2, %0;" : "+l"(d) : "l"(a), "l"(b));
}

__global__ __launch_bounds__(THREADS, 1)
void router_kernel(const float* __restrict__ x,
                   const float* __restrict__ w,
                   float* __restrict__ out,
                   int tokens) {
    // staging: xs[TPC][XPAD] token-major, ws[KC][EPAD] k-major (experts contig)
    __shared__ float smem[TPC * XPAD + KC * EPAD];
    float* xs = smem;
    float* ws = smem + TPC * XPAD;
    __shared__ float sm_m[TPC];     // per-token max
    __shared__ float sm_is[TPC];    // per-token 1/sum(exp)
    __shared__ int   cnt_s[NEXP];
    __shared__ float red_s[2];

    const int tid  = threadIdx.x;
    const int cta  = blockIdx.x;
    const int tok0 = cta * TPC;

    const int et = tid & 7;    // expert group: experts [et*8, et*8+8)
    const int tt = tid >> 3;   // token group:  tokens  [tt*4, tt*4+4)

    unsigned long long acc[4][4];
#pragma unroll
    for (int i = 0; i < 4; i++)
#pragma unroll
        for (int p = 0; p < 4; p++) acc[i][p] = 0ull;

    const float2* xg = (const float2*)(x + (size_t)tok0 * DIM);
    const float2* wg = (const float2*)w;

    float2 xr[16], wr[16];

    // prefetch chunk 0
#pragma unroll
    for (int i = 0; i < 16; i++) {
        int idx = i * THREADS + tid;
        int row = idx >> 5;          // token (x) / expert (w)
        int kq  = idx & 31;          // float2 index within chunk
        xr[i] = xg[(size_t)row * (DIM / 2) + kq];
        wr[i] = wg[(size_t)row * (DIM / 2) + kq];
    }

    for (int c = 0; c < NCHUNK; c++) {
        __syncthreads();   // previous compute done; smem free
        // store staged registers to smem (w transposed to k-major)
#pragma unroll
        for (int i = 0; i < 16; i++) {
            int idx = i * THREADS + tid;
            int row = idx >> 5;
            int kq  = idx & 31;
            *(float2*)&xs[row * XPAD + kq * 2] = xr[i];
            ws[(kq * 2    ) * EPAD + row] = wr[i].x;
            ws[(kq * 2 + 1) * EPAD + row] = wr[i].y;
        }
        // prefetch next chunk (LDGs in flight during compute below)
        if (c + 1 < NCHUNK) {
            int kc2 = (c + 1) * (KC / 2);
#pragma unroll
            for (int i = 0; i < 16; i++) {
                int idx = i * THREADS + tid;
                int row = idx >> 5;
                int kq  = idx & 31;
                xr[i] = xg[(size_t)row * (DIM / 2) + kc2 + kq];
                wr[i] = wg[(size_t)row * (DIM / 2) + kc2 + kq];
            }
        }
        __syncthreads();   // staging visible
        // compute: 4 tokens x 8 experts per thread, packed fp32
#pragma unroll 4
        for (int k = 0; k < KC; k++) {
            unsigned long long xb[4];
#pragma unroll
            for (int i = 0; i < 4; i++) {
                float xv = xs[(tt * 4 + i) * XPAD + k];
                xb[i] = pack2(xv, xv);
            }
            unsigned long long wv[4];
#pragma unroll
            for (int p = 0; p < 4; p++)
                wv[p] = *(const unsigned long long*)&ws[k * EPAD + et * 8 + p * 2];
#pragma unroll
            for (int i = 0; i < 4; i++)
#pragma unroll
                for (int p = 0; p < 4; p++) fma2(acc[i][p], xb[i], wv[p]);
        }
    }

    // ---- epilogue: logits -> smem (reuse staging region), padded rows ----
    __syncthreads();                 // all compute reads of xs/ws done
    float* L = smem;                 // [TPC][66]
#pragma unroll
    for (int i = 0; i < 4; i++)
#pragma unroll
        for (int p = 0; p < 4; p++) {
            float2 v = unpack2(acc[i][p]);
            *(float2*)&L[(tt * 4 + i) * 66 + et * 8 + p * 2] = v;
        }
    if (tid < NEXP) cnt_s[tid] = 0;
    __syncthreads();

    // ---- pass A: per-token softmax stats, top-2, outputs, z-term ----
    if (tid < TPC) {
        const int t = tid;
        const float* Lr = &L[t * 66];
        float v1 = -3.402823466e38f, v2 = -3.402823466e38f;
        int i1 = 0, i2 = 0;
#pragma unroll 8
        for (int e = 0; e < NEXP; e++) {
            float l = Lr[e];
            if (l > v1) { v2 = v1; i2 = i1; v1 = l; i1 = e; }
            else if (l > v2) { v2 = l; i2 = e; }
        }
        float S = 0.f;
#pragma unroll 8
        for (int e = 0; e < NEXP; e++) S += __expf(Lr[e] - v1);
        float invS = 1.f / S;
        sm_m[t]  = v1;
        sm_is[t] = invS;

        float lse  = v1 + __logf(S);
        float lse2 = lse * lse;
#pragma unroll
        for (int o = 16; o > 0; o >>= 1)
            lse2 += __shfl_down_sync(0xffffffffu, lse2, o);
        if ((tid & 31) == 0) red_s[tid >> 5] = lse2;

        // renormalized top-2 weights: e1/(e1+e2), e2/(e1+e2), e1 = 1
        float e2   = __expf(v2 - v1);
        float inv  = 1.f / (1.f + e2);
        int gt = tok0 + t;
        out[gt * 2    ] = (float)i1;
        out[gt * 2 + 1] = (float)i2;
        float* wout = out + 2 * tokens;
        wout[gt * 2    ] = inv;
        wout[gt * 2 + 1] = e2 * inv;

        atomicAdd(&cnt_s[i1], 1);    // integer smem atomics: deterministic
        atomicAdd(&cnt_s[i2], 1);
    }
    __syncthreads();

    // ---- pass B: per-expert softmax-weight partial sums (fixed order) ----
    if (tid < NEXP) {
        const int e = tid;
        float P = 0.f;
#pragma unroll 8
        for (int t = 0; t < TPC; t++)
            P += __expf(L[t * 66 + e] - sm_m[t]) * sm_is[t];
        g_P[cta * NEXP + e]   = P;
        g_cnt[cta * NEXP + e] = cnt_s[e];
    }
    if (tid == 0) g_lse2[cta] = red_s[0] + red_s[1];
}

__global__ void finalize_kernel(float* __restrict__ out, int tokens, int nCta) {
    __shared__ float redT[2], redZ[2];
    const int e = threadIdx.x;   // 64 threads
    float P = 0.f, cnt = 0.f;
    for (int c = 0; c < nCta; c++) {            // fixed order -> deterministic
        P   += g_P[c * NEXP + e];
        cnt += (float)g_cnt[c * NEXP + e];
    }
    float f    = cnt / (float)(tokens * 2);
    float Pm   = P / (float)tokens;
    float term = f * Pm;

    float z = 0.f;
    for (int c = e; c < nCta; c += NEXP) z += g_lse2[c];

#pragma unroll
    for (int o = 16; o > 0; o >>= 1) {
        term += __shfl_down_sync(0xffffffffu, term, o);
        z    += __shfl_down_sync(0xffffffffu, z, o);
    }
    if ((e & 31) == 0) { redT[e >> 5] = term; redZ[e >> 5] = z; }
    __syncthreads();
    if (e == 0) {
        float balance = (float)NEXP * (redT[0] + redT[1]);
        float zloss   = (redZ[0] + redZ[1]) / (float)tokens;
        out[4 * tokens] = 0.01f * balance + 0.001f * zloss;
    }
}

extern "C" void kernel_launch(void* const* d_in, const int* in_sizes, int n_in,
                              void* d_out, int out_size) {
    const float* x = (const float*)d_in[0];
    const float* w = (const float*)d_in[1];
    float* out = (float*)d_out;
    int tokens = in_sizes[0] / DIM;       // 16384
    int nCta   = tokens / TPC;            // 256
    router_kernel<<<nCta, THREADS>>>(x, w, out, tokens);
    finalize_kernel<<<1, NEXP>>>(out, tokens, nCta);
}

// round 3
// speedup vs baseline: 2.6673x; 2.6673x over previous
#include <cuda_runtime.h>
#include <cuda_fp16.h>
#include <cstdint>

// ---------------------------------------------------------------------------
// TopKRouter via 2-limb fp16 split + mma.sync m16n8k16 (compute_100-safe).
// logits = x @ w^T ; softmax ; top-2 (+renorm) ; aux loss.
// x: [T=16384, D=2048] fp32, w: [E=64, D=2048] fp32.
// out (fp32, 4T+1): [indices(2T) | weights(2T) | aux_loss]
// ---------------------------------------------------------------------------

#define DIM     2048
#define NEXP    64
#define CTAM    128           // tokens per CTA
#define KC      32            // K per chunk
#define NCHUNK  (DIM / KC)    // 64
#define THREADS 256
#define MAXCTA  1024

// smem: per buffer: A limb0, A limb1 (128 x 40 halves = 10240 B each),
//                   B limb0, B limb1 (64 x 40 halves = 5120 B each)
#define PADH    40                         // halves per row (80 B)
#define SA_OFF(buf, l)  ((buf) * 30720 + (l) * 10240)
#define SB_OFF(buf, l)  ((buf) * 30720 + 20480 + (l) * 5120)
#define SMEM_BYTES      61440

__device__ unsigned short g_w0[NEXP * DIM];
__device__ unsigned short g_w1[NEXP * DIM];
__device__ float g_P[MAXCTA * NEXP];
__device__ int   g_cnt[MAXCTA * NEXP];
__device__ float g_lse2[MAXCTA];

__device__ __forceinline__ uint32_t smem_u32(const void* p) {
    uint32_t a;
    asm("{ .reg .u64 t; cvta.to.shared.u64 t, %1; cvt.u32.u64 %0, t; }" : "=r"(a) : "l"(p));
    return a;
}
__device__ __forceinline__ void ldsm4(uint32_t* r, uint32_t a) {
    asm volatile("ldmatrix.sync.aligned.m8n8.x4.shared.b16 {%0,%1,%2,%3}, [%4];"
                 : "=r"(r[0]), "=r"(r[1]), "=r"(r[2]), "=r"(r[3]) : "r"(a));
}
__device__ __forceinline__ void mma16816(float* c, const uint32_t* a, uint32_t b0, uint32_t b1) {
    asm volatile("mma.sync.aligned.m16n8k16.row.col.f32.f16.f16.f32 "
                 "{%0,%1,%2,%3},{%4,%5,%6,%7},{%8,%9},{%0,%1,%2,%3};"
                 : "+f"(c[0]), "+f"(c[1]), "+f"(c[2]), "+f"(c[3])
                 : "r"(a[0]), "r"(a[1]), "r"(a[2]), "r"(a[3]), "r"(b0), "r"(b1));
}
// round-nearest 2-limb fp16 split of a float pair -> packed half2 limbs
__device__ __forceinline__ void split2(float f0, float f1, uint32_t& l0, uint32_t& l1) {
    __half2 h0 = __floats2half2_rn(f0, f1);
    float2 g = __half22float2(h0);
    __half2 h1 = __floats2half2_rn(f0 - g.x, f1 - g.y);
    l0 = *(uint32_t*)&h0;
    l1 = *(uint32_t*)&h1;
}

// ---------------- prep: split gate_w into fp16 limbs ----------------
__global__ void prep_kernel(const float* __restrict__ w) {
    int i = blockIdx.x * 256 + threadIdx.x;       // 64*2048 total
    float f = w[i];
    __half h0 = __float2half_rn(f);
    float r = f - __half2float(h0);
    __half h1 = __float2half_rn(r);
    g_w0[i] = *(unsigned short*)&h0;
    g_w1[i] = *(unsigned short*)&h1;
}

// ---------------- main router ----------------
__global__ __launch_bounds__(THREADS, 1)
void router_kernel(const float* __restrict__ x, float* __restrict__ out, int tokens) {
    extern __shared__ char smem[];
    const uint32_t sb = smem_u32(smem);
    const int tid = threadIdx.x, w = tid >> 5, lane = tid & 31;
    const int cta = blockIdx.x, tok0 = cta * CTAM;

    __shared__ float sm_m[CTAM];
    __shared__ float sm_is[CTAM];
    __shared__ int   cnt_s[NEXP];
    __shared__ float red_s[4];

    // ---- GEMM mainloop (double-buffered, 1 sync/chunk) ----
    const float4* xg = (const float4*)(x + (size_t)tok0 * DIM);
    // x staging map: idx = i*256+tid ; row = idx/8 (128), col4 = idx%8 (8 float4/row)
    int rowx[4], c4x[4];
    float4 xv[4];
#pragma unroll
    for (int i = 0; i < 4; i++) {
        int idx = i * THREADS + tid;
        rowx[i] = idx >> 3; c4x[i] = idx & 7;
        xv[i] = xg[(size_t)rowx[i] * (DIM / 4) + c4x[i]];         // chunk 0
    }
    // w staging map: expert = tid/4, k-group = (tid%4)*8 halves
    const int er = tid >> 2, kg = (tid & 3) * 8;
    uint4 wv0 = *(const uint4*)&g_w0[er * DIM + kg];
    uint4 wv1 = *(const uint4*)&g_w1[er * DIM + kg];

    float acc[8][4];
#pragma unroll
    for (int nb = 0; nb < 8; nb++)
#pragma unroll
        for (int j = 0; j < 4; j++) acc[nb][j] = 0.f;

    // ldmatrix lane address components (byte offsets within a tile)
    const uint32_t aRow = (uint32_t)(w * 16 + (lane & 15)) * (PADH * 2) + (lane >> 4) * 16;
    const uint32_t bRow = (uint32_t)((lane & 7) + ((lane >> 4) & 1) * 8) * (PADH * 2)
                        + ((lane >> 3) & 1) * 16;

    for (int c = 0; c < NCHUNK; c++) {
        const int buf = c & 1;
        // store x limbs
#pragma unroll
        for (int i = 0; i < 4; i++) {
            uint32_t p0, p1, q0, q1;
            split2(xv[i].x, xv[i].y, p0, q0);
            split2(xv[i].z, xv[i].w, p1, q1);
            uint32_t off = (uint32_t)rowx[i] * (PADH * 2) + c4x[i] * 8;
            *(uint2*)(smem + SA_OFF(buf, 0) + off) = make_uint2(p0, p1);
            *(uint2*)(smem + SA_OFF(buf, 1) + off) = make_uint2(q0, q1);
        }
        // store w limbs
        {
            uint32_t off = (uint32_t)er * (PADH * 2) + kg * 2;
            *(uint4*)(smem + SB_OFF(buf, 0) + off) = wv0;
            *(uint4*)(smem + SB_OFF(buf, 1) + off) = wv1;
        }
        __syncthreads();
        // prefetch next chunk
        if (c + 1 < NCHUNK) {
            int k4 = (c + 1) * (KC / 4), kw = (c + 1) * KC;
#pragma unroll
            for (int i = 0; i < 4; i++)
                xv[i] = xg[(size_t)rowx[i] * (DIM / 4) + k4 + c4x[i]];
            wv0 = *(const uint4*)&g_w0[er * DIM + kw + kg];
            wv1 = *(const uint4*)&g_w1[er * DIM + kw + kg];
        }
        // compute: 2 k-steps of m16n8k16
        const uint32_t a0b = sb + SA_OFF(buf, 0) + aRow;
        const uint32_t a1b = sb + SA_OFF(buf, 1) + aRow;
        const uint32_t b0b = sb + SB_OFF(buf, 0) + bRow;
        const uint32_t b1b = sb + SB_OFF(buf, 1) + bRow;
#pragma unroll
        for (int ks = 0; ks < 2; ks++) {
            uint32_t af0[4], af1[4];
            ldsm4(af0, a0b + ks * 32);
            ldsm4(af1, a1b + ks * 32);
#pragma unroll
            for (int lb = 0; lb < 2; lb++) {
                uint32_t bb = (lb ? b1b : b0b) + ks * 32;
#pragma unroll
                for (int nb2 = 0; nb2 < 4; nb2++) {
                    uint32_t bf[4];
                    ldsm4(bf, bb + nb2 * 16 * (PADH * 2));
                    mma16816(acc[nb2 * 2    ], af0, bf[0], bf[1]);
                    mma16816(acc[nb2 * 2    ], af1, bf[0], bf[1]);
                    mma16816(acc[nb2 * 2 + 1], af0, bf[2], bf[3]);
                    mma16816(acc[nb2 * 2 + 1], af1, bf[2], bf[3]);
                }
            }
        }
    }
    __syncthreads();   // all tensor work done; smem free for logits overlay

    // ---- epilogue: accumulators -> smem logits [128][66] ----
    float* L = (float*)smem;
    {
        int r0 = w * 16 + (lane >> 2);
        int cb = (lane & 3) * 2;
#pragma unroll
        for (int nb = 0; nb < 8; nb++) {
            *(float2*)&L[r0 * 66 + nb * 8 + cb]       = make_float2(acc[nb][0], acc[nb][1]);
            *(float2*)&L[(r0 + 8) * 66 + nb * 8 + cb] = make_float2(acc[nb][2], acc[nb][3]);
        }
    }
    if (tid < NEXP) cnt_s[tid] = 0;
    __syncthreads();

    // ---- pass A: per-token top-2, softmax stats, outputs, z ----
    if (tid < CTAM) {
        const int t = tid;
        const float* Lr = &L[t * 66];
        float v1 = -3.402823466e38f, v2 = -3.402823466e38f;
        int i1 = 0, i2 = 0;
#pragma unroll 8
        for (int e = 0; e < NEXP; e++) {
            float l = Lr[e];
            if (l > v1) { v2 = v1; i2 = i1; v1 = l; i1 = e; }
            else if (l > v2) { v2 = l; i2 = e; }
        }
        float S = 0.f;
#pragma unroll 8
        for (int e = 0; e < NEXP; e++) S += __expf(Lr[e] - v1);
        float invS = 1.f / S;
        sm_m[t] = v1; sm_is[t] = invS;

        float lse = v1 + __logf(S);
        float z2 = lse * lse;
#pragma unroll
        for (int o = 16; o > 0; o >>= 1) z2 += __shfl_down_sync(0xffffffffu, z2, o);
        if ((t & 31) == 0) red_s[t >> 5] = z2;

        float e2 = __expf(v2 - v1);
        float inv = 1.f / (1.f + e2);
        int gt = tok0 + t;
        out[gt * 2    ] = (float)i1;
        out[gt * 2 + 1] = (float)i2;
        float* wout = out + 2 * tokens;
        wout[gt * 2    ] = inv;
        wout[gt * 2 + 1] = e2 * inv;
        atomicAdd(&cnt_s[i1], 1);
        atomicAdd(&cnt_s[i2], 1);
    }
    __syncthreads();

    // ---- pass B: per-expert softmax-weight partials (fixed order) ----
    if (tid < NEXP) {
        const int e = tid;
        float P = 0.f;
#pragma unroll 8
        for (int t = 0; t < CTAM; t++)
            P += __expf(L[t * 66 + e] - sm_m[t]) * sm_is[t];
        g_P[cta * NEXP + e]   = P;
        g_cnt[cta * NEXP + e] = cnt_s[e];
    }
    if (tid == 0) g_lse2[cta] = ((red_s[0] + red_s[1]) + red_s[2]) + red_s[3];
}

// ---------------- finalize: deterministic global reduction ----------------
__global__ void finalize_kernel(float* __restrict__ out, int tokens, int nCta) {
    __shared__ float sP[16][NEXP];
    __shared__ float sC[16][NEXP];
    __shared__ float sZ[256];
    __shared__ float sT[NEXP];
    const int tid = threadIdx.x;            // 1024
    const int s = tid >> 6, e = tid & 63;
    float P = 0.f, C = 0.f;
    for (int c = s; c < nCta; c += 16) {    // fixed order per slice
        P += g_P[c * NEXP + e];
        C += (float)g_cnt[c * NEXP + e];
    }
    sP[s][e] = P; sC[s][e] = C;
    if (tid < 256) sZ[tid] = (tid < nCta) ? g_lse2[tid] : 0.f;
    __syncthreads();
    if (tid < NEXP) {
        float p = 0.f, c2 = 0.f;
#pragma unroll
        for (int s2 = 0; s2 < 16; s2++) { p += sP[s2][tid]; c2 += sC[s2][tid]; }
        float f  = c2 / (float)(tokens * 2);
        float Pm = p / (float)tokens;
        sT[tid] = f * Pm;
    }
    __syncthreads();
    if (tid == 0) {
        float t = 0.f;
        for (int e2 = 0; e2 < NEXP; e2++) t += sT[e2];
        float z = 0.f;
        for (int i = 0; i < 256; i++) z += sZ[i];
        out[4 * tokens] = 0.01f * ((float)NEXP * t) + 0.001f * (z / (float)tokens);
    }
}

extern "C" void kernel_launch(void* const* d_in, const int* in_sizes, int n_in,
                              void* d_out, int out_size) {
    const float* x = (const float*)d_in[0];
    const float* w = (const float*)d_in[1];
    float* out = (float*)d_out;
    int tokens = in_sizes[0] / DIM;         // 16384
    int nCta   = tokens / CTAM;             // 128
    static int configured = 0;
    cudaFuncSetAttribute(router_kernel, cudaFuncAttributeMaxDynamicSharedMemorySize, SMEM_BYTES);
    (void)configured;
    prep_kernel<<<(NEXP * DIM) / 256, 256>>>(w);
    router_kernel<<<nCta, THREADS, SMEM_BYTES>>>(x, out, tokens);
    finalize_kernel<<<1, 1024>>>(out, tokens, nCta);
}